// round 1
// baseline (speedup 1.0000x reference)
#include <cuda_runtime.h>

// ---------------------------------------------------------------------------
// VectorQuantizer on GB300.
// Inputs:  latents [16,64,64,64] NCHW fp32, emb_weight [1024,64] fp32
// Output (flattened concat, fp32):
//   quantize   [16,64,64,64]   4194304   @ 0
//   vq_loss    scalar          1         @ 4194304
//   perplexity scalar          1         @ 4194305
//   encodings  [65536,1024]    67108864  @ 4194306
//   inds       [65536,1]       65536     @ 71303170
//   distances  [65536,1024]    67108864  @ 71368706
// ---------------------------------------------------------------------------

#define NPTS   65536
#define KCODES 1024
#define DDIM   64

static const long long Q_OFF     = 0LL;
static const long long LOSS_OFF  = 4194304LL;
static const long long PERP_OFF  = 4194305LL;
static const long long ENC_OFF   = 4194306LL;
static const long long INDS_OFF  = 71303170LL;
static const long long DIST_OFF  = 71368706LL;
static const long long TOTAL_OUT = 138477570LL;

__device__ int    g_counts[KCODES];
__device__ float  g_esq[KCODES];
__device__ double g_mse;

// packed fp32x2 FMA (Blackwell; ptxas never auto-fuses this from C++)
#define FMA2(d, a, b, c) \
    asm("fma.rn.f32x2 %0, %1, %2, %3;" : "=l"(d) : "l"(a), "l"(b), "l"(c))
#define PACKDUP(d, f) \
    asm("mov.b64 %0, {%1, %1};" : "=l"(d) : "r"(__float_as_uint(f)))

__device__ __forceinline__ float2 unpack2(unsigned long long v) {
    unsigned int lo, hi;
    asm("mov.b64 {%0, %1}, %2;" : "=r"(lo), "=r"(hi) : "l"(v));
    return make_float2(__uint_as_float(lo), __uint_as_float(hi));
}

// ---------------------------------------------------------------------------
// Kernel 0: reset accumulators, precompute ||e_k||^2
// ---------------------------------------------------------------------------
__global__ void vq_prep(const float* __restrict__ emb) {
    int k = blockIdx.x * blockDim.x + threadIdx.x;
    if (k == 0) g_mse = 0.0;
    if (k < KCODES) {
        g_counts[k] = 0;
        const float* row = emb + k * DDIM;
        float s = 0.f;
        #pragma unroll
        for (int d = 0; d < DDIM; ++d) { float v = row[d]; s += v * v; }
        g_esq[k] = s;
    }
}

// ---------------------------------------------------------------------------
// Kernel 1: main. Block = 64 rows x 1024 codes. 256 threads.
// Thread micro-tile: 4 rows x 4 codes, f32x2-packed accumulators.
// ---------------------------------------------------------------------------
template <bool FULL>
__global__ void __launch_bounds__(256)
vq_main(const float* __restrict__ lat, const float* __restrict__ emb,
        float* __restrict__ out) {
    __shared__ float sx[64][68];     // x tile transposed: [d][row]
    __shared__ float se[64][68];     // emb chunk transposed: [d][code]
    __shared__ float xsq[64];
    __shared__ float rmin[64][16];
    __shared__ int   ridx[64][16];
    __shared__ int   sind[64];
    __shared__ float smse[64];

    const int tid = threadIdx.x;
    const int n0  = blockIdx.x * 64;        // first row of this block
    const int b   = n0 >> 12;               // batch index (4096 hw per batch)
    const int hw0 = n0 & 4095;
    const int rg  = tid >> 4;                // row group 0..15   (rows rg*4..rg*4+3)
    const int cg  = tid & 15;                // code group 0..15  (codes cg*4..cg*4+3)

    // load x tile: latents NCHW -> sx[d][r]  (coalesced over r)
    #pragma unroll
    for (int i = 0; i < 16; ++i) {
        int idx = tid + i * 256;
        int d = idx >> 6, r = idx & 63;
        sx[d][r] = lat[(long long)b * 262144 + (long long)d * 4096 + hw0 + r];
    }
    __syncthreads();
    if (tid < 64) {
        float s = 0.f;
        #pragma unroll
        for (int d = 0; d < 64; ++d) { float v = sx[d][tid]; s += v * v; }
        xsq[tid] = s;
    }

    float bestv[4] = {3.4e38f, 3.4e38f, 3.4e38f, 3.4e38f};
    int   besti[4] = {0, 0, 0, 0};

    for (int kc = 0; kc < KCODES / 64; ++kc) {
        const int kbase = kc * 64;
        __syncthreads();   // protect se from previous iter / xsq on first iter
        // load emb chunk transposed (coalesced global read over d)
        #pragma unroll
        for (int i = 0; i < 16; ++i) {
            int idx = tid + i * 256;
            int c = idx >> 6, d = idx & 63;
            se[d][c] = emb[(kbase + c) * 64 + d];
        }
        __syncthreads();

        unsigned long long acc[4][2];
        #pragma unroll
        for (int i = 0; i < 4; ++i) { acc[i][0] = 0ULL; acc[i][1] = 0ULL; }

        #pragma unroll 8
        for (int d = 0; d < 64; ++d) {
            const float4     xv = *(const float4*)&sx[d][rg * 4];
            const ulonglong2 ev = *(const ulonglong2*)&se[d][cg * 4];
            float xf[4] = {xv.x, xv.y, xv.z, xv.w};
            #pragma unroll
            for (int i = 0; i < 4; ++i) {
                unsigned long long xp;
                PACKDUP(xp, xf[i]);
                FMA2(acc[i][0], xp, ev.x, acc[i][0]);
                FMA2(acc[i][1], xp, ev.y, acc[i][1]);
            }
        }

        const float4 eq = *(const float4*)&g_esq[kbase + cg * 4];
        const int cbase = kbase + cg * 4;
        #pragma unroll
        for (int i = 0; i < 4; ++i) {
            float xs = xsq[rg * 4 + i];
            float2 p0 = unpack2(acc[i][0]);
            float2 p1 = unpack2(acc[i][1]);
            float d0 = xs + eq.x - 2.f * p0.x;
            float d1 = xs + eq.y - 2.f * p0.y;
            float d2 = xs + eq.z - 2.f * p1.x;
            float d3 = xs + eq.w - 2.f * p1.y;
            // first-min tie-break: strict <, ascending code order
            if (d0 < bestv[i]) { bestv[i] = d0; besti[i] = cbase;     }
            if (d1 < bestv[i]) { bestv[i] = d1; besti[i] = cbase + 1; }
            if (d2 < bestv[i]) { bestv[i] = d2; besti[i] = cbase + 2; }
            if (d3 < bestv[i]) { bestv[i] = d3; besti[i] = cbase + 3; }
            if (FULL) {
                long long n    = n0 + rg * 4 + i;
                long long base = n * 1024 + cbase;
                *(float2*)(out + DIST_OFF + base)     = make_float2(d0, d1);
                *(float2*)(out + DIST_OFF + base + 2) = make_float2(d2, d3);
                *(float2*)(out + ENC_OFF  + base)     = make_float2(0.f, 0.f);
                *(float2*)(out + ENC_OFF  + base + 2) = make_float2(0.f, 0.f);
            }
        }
    }

    // cross-thread argmin reduce per row
    #pragma unroll
    for (int i = 0; i < 4; ++i) {
        rmin[rg * 4 + i][cg] = bestv[i];
        ridx[rg * 4 + i][cg] = besti[i];
    }
    __syncthreads();

    if (tid < 64) {
        float bv = rmin[tid][0];
        int   bi = ridx[tid][0];
        #pragma unroll
        for (int j = 1; j < 16; ++j) {
            float v = rmin[tid][j];
            int   x = ridx[tid][j];
            if (v < bv || (v == bv && x < bi)) { bv = v; bi = x; }
        }
        sind[tid] = bi;
        smse[tid] = bv;                 // min distance == ||x - e||^2 (same expansion)
        int n = n0 + tid;
        atomicAdd(&g_counts[bi], 1);
        if (FULL) {
            out[INDS_OFF + n] = (float)bi;
            out[ENC_OFF + (long long)n * 1024 + bi] = 1.0f;  // after zeros (same block)
        }
    }
    __syncthreads();

    // block MSE partial -> single double atomic
    if (tid < 32) {
        float s = smse[tid] + smse[tid + 32];
        #pragma unroll
        for (int off = 16; off > 0; off >>= 1)
            s += __shfl_down_sync(0xffffffffu, s, off);
        if (tid == 0) atomicAdd(&g_mse, (double)s);
    }

    // quantize gather: out NCHW[b][d][hw0+r] = emb[ind[r]][d]  (coalesced over r)
    #pragma unroll
    for (int i = 0; i < 16; ++i) {
        int idx = tid + i * 256;
        int r = idx & 63, d = idx >> 6;
        out[Q_OFF + (long long)b * 262144 + (long long)d * 4096 + hw0 + r] =
            emb[sind[r] * 64 + d];
    }
}

// ---------------------------------------------------------------------------
// Kernel 2: loss + perplexity
// ---------------------------------------------------------------------------
__global__ void vq_finalize(float* __restrict__ out) {
    __shared__ float red[32];
    int t = threadIdx.x;                     // 1024 threads
    float p = (float)g_counts[t] * (1.0f / 65536.0f);
    float v = p * logf(p + 1e-10f);
    #pragma unroll
    for (int off = 16; off > 0; off >>= 1)
        v += __shfl_down_sync(0xffffffffu, v, off);
    if ((t & 31) == 0) red[t >> 5] = v;
    __syncthreads();
    if (t < 32) {
        float s = red[t];
        #pragma unroll
        for (int off = 16; off > 0; off >>= 1)
            s += __shfl_down_sync(0xffffffffu, s, off);
        if (t == 0) {
            out[PERP_OFF] = expf(-s);
            // vq_loss = beta*mse + mse = 1.25 * mean(min_dist)
            out[LOSS_OFF] = (float)(g_mse * (1.25 / (65536.0 * 64.0)));
        }
    }
}

// ---------------------------------------------------------------------------
extern "C" void kernel_launch(void* const* d_in, const int* in_sizes, int n_in,
                              void* d_out, int out_size) {
    const float* lat = (const float*)d_in[0];
    const float* emb = (const float*)d_in[1];
    if (n_in >= 2 && in_sizes[0] == KCODES * DDIM && in_sizes[1] == NPTS * DDIM) {
        lat = (const float*)d_in[1];
        emb = (const float*)d_in[0];
    }
    float* out = (float*)d_out;
    const bool full = ((long long)out_size >= TOTAL_OUT);

    vq_prep<<<4, 256>>>(emb);
    if (full) {
        vq_main<true><<<1024, 256>>>(lat, emb, out);
        vq_finalize<<<1, 1024>>>(out);
    } else {
        vq_main<false><<<1024, 256>>>(lat, emb, out);
    }
}